// round 7
// baseline (speedup 1.0000x reference)
#include <cuda_runtime.h>
#include <cuda_bf16.h>
#include <cstdint>

#define N_NODES 100000
#define E_EDGES 1600000
#define D 64

#define SCAN_T 256
#define SCAN_ELEMS 2048                 // 8 per thread
#define NB_SCAN ((N_NODES + SCAN_ELEMS - 1) / SCAN_ELEMS)   // 49

// ---------------- scratch (device globals; no allocation allowed) ----------
__device__ int   g_cnt[N_NODES];
__device__ int   g_off[N_NODES + 1];
__device__ int   g_cursor[N_NODES];
__device__ int   g_src_sorted[E_EDGES];
__device__ int   g_partial[64];
__device__ int   g_is64;                 // 1 if edge_index is int64, 0 if int32
__device__ float g_y[(size_t)N_NODES * D];
__device__ float g_z[(size_t)N_NODES * D];
__device__ float g_h[(size_t)N_NODES * D];

// ---------------- edge_index layout probe ----------------------------------
// If data is int64 (values < 2^31), every high 32-bit word is 0.
// If data is int32, the "high words" are random indices — nonzero w.h.p.
__global__ void k_detect(const int* __restrict__ ei32) {
    if (threadIdx.x == 0 && blockIdx.x == 0) {
        int nz_hi = 0;
#pragma unroll 1
        for (int k = 0; k < 64; k++) {
            if (ei32[2 * k + 1] != 0) nz_hi++;
        }
        g_is64 = (nz_hi == 0) ? 1 : 0;
    }
}

__device__ __forceinline__ int edge_val(const int* ei32, long long idx) {
    // idx in [0, 2E): flat index into logical int array of edge_index
    if (g_is64) {
        return (int)((const long long*)ei32)[idx];
    }
    return ei32[idx];
}

// ---------------- CSR build ------------------------------------------------
__global__ void k_zero_cnt() {
    int i = blockIdx.x * blockDim.x + threadIdx.x;
    if (i < N_NODES) g_cnt[i] = 0;
}

__global__ void k_hist(const int* __restrict__ ei32) {
    int e = blockIdx.x * blockDim.x + threadIdx.x;
    if (e < E_EDGES) {
        int d = edge_val(ei32, (long long)E_EDGES + e);   // dst row
        atomicAdd(&g_cnt[d], 1);
    }
}

__global__ void k_scan1() {
    int base = blockIdx.x * SCAN_ELEMS + threadIdx.x * 8;
    int s = 0;
#pragma unroll
    for (int u = 0; u < 8; u++) {
        int i = base + u;
        if (i < N_NODES) s += g_cnt[i];
    }
    __shared__ int sh[SCAN_T];
    sh[threadIdx.x] = s;
    __syncthreads();
    for (int st = SCAN_T / 2; st > 0; st >>= 1) {
        if (threadIdx.x < st) sh[threadIdx.x] += sh[threadIdx.x + st];
        __syncthreads();
    }
    if (threadIdx.x == 0) g_partial[blockIdx.x] = sh[0];
}

__global__ void k_scan2() {
    if (threadIdx.x == 0 && blockIdx.x == 0) {
        int acc = 0;
        for (int b = 0; b < NB_SCAN; b++) {
            int v = g_partial[b];
            g_partial[b] = acc;
            acc += v;
        }
        g_off[N_NODES] = acc;   // == E_EDGES
    }
}

__global__ void k_scan3() {
    __shared__ int sh[SCAN_T];
    int base = blockIdx.x * SCAN_ELEMS + threadIdx.x * 8;
    int loc[8];
    int s = 0;
#pragma unroll
    for (int u = 0; u < 8; u++) {
        int i = base + u;
        loc[u] = (i < N_NODES) ? g_cnt[i] : 0;
        s += loc[u];
    }
    sh[threadIdx.x] = s;
    __syncthreads();
    // Hillis-Steele inclusive scan over thread sums
    for (int st = 1; st < SCAN_T; st <<= 1) {
        int v = 0;
        if (threadIdx.x >= st) v = sh[threadIdx.x - st];
        __syncthreads();
        sh[threadIdx.x] += v;
        __syncthreads();
    }
    int pre = g_partial[blockIdx.x] + sh[threadIdx.x] - s;  // exclusive prefix
#pragma unroll
    for (int u = 0; u < 8; u++) {
        int i = base + u;
        if (i < N_NODES) {
            g_off[i] = pre;
            g_cursor[i] = pre;
            pre += loc[u];
        }
    }
}

__global__ void k_scatter(const int* __restrict__ ei32) {
    int e = blockIdx.x * blockDim.x + threadIdx.x;
    if (e < E_EDGES) {
        int d = edge_val(ei32, (long long)E_EDGES + e);
        int s = edge_val(ei32, e);
        int p = atomicAdd(&g_cursor[d], 1);
        g_src_sorted[p] = s;
    }
}

// ---------------- fused dual GEMM: Y = X @ Wl^T, Z = X @ Wr^T --------------
// One thread per node row. Weights staged in smem, float4 weight loads so the
// inner loop is 4 FFMA per LDS.128 (FFMA-bound, not LDS-bound).
// LAYER==0 reads the harness input X; LAYER==1 reads g_h. Writes g_y/g_z.
template <int LAYER>
__global__ void __launch_bounds__(256) k_gemm_dual(
    const float* __restrict__ Xin,
    const float* __restrict__ Wl,   // [64,64] row-major [out,in]
    const float* __restrict__ Wr)
{
    __shared__ float swl[D * D];
    __shared__ float swr[D * D];
    for (int i = threadIdx.x; i < D * D; i += blockDim.x) {
        swl[i] = Wl[i];
        swr[i] = Wr[i];
    }
    __syncthreads();

    int row = blockIdx.x * blockDim.x + threadIdx.x;
    if (row >= N_NODES) return;

    const float* X = (LAYER == 0) ? Xin : (const float*)g_h;

    float4 xv[16];
    const float4* xp = (const float4*)(X + (size_t)row * D);
#pragma unroll
    for (int k4 = 0; k4 < 16; k4++) xv[k4] = xp[k4];

    float* outY = g_y + (size_t)row * D;
    float* outZ = g_z + (size_t)row * D;

#pragma unroll 1
    for (int f0 = 0; f0 < D; f0 += 8) {
        float acc[8];
#pragma unroll
        for (int u = 0; u < 8; u++) acc[u] = 0.0f;
#pragma unroll
        for (int k4 = 0; k4 < 16; k4++) {
            float4 xk = xv[k4];
#pragma unroll
            for (int u = 0; u < 8; u++) {
                float4 w = *(const float4*)&swl[(f0 + u) * D + k4 * 4];
                acc[u] += xk.x * w.x + xk.y * w.y + xk.z * w.z + xk.w * w.w;
            }
        }
#pragma unroll
        for (int u = 0; u < 8; u++) outY[f0 + u] = acc[u];
    }

#pragma unroll 1
    for (int f0 = 0; f0 < D; f0 += 8) {
        float acc[8];
#pragma unroll
        for (int u = 0; u < 8; u++) acc[u] = 0.0f;
#pragma unroll
        for (int k4 = 0; k4 < 16; k4++) {
            float4 xk = xv[k4];
#pragma unroll
            for (int u = 0; u < 8; u++) {
                float4 w = *(const float4*)&swr[(f0 + u) * D + k4 * 4];
                acc[u] += xk.x * w.x + xk.y * w.y + xk.z * w.z + xk.w * w.w;
            }
        }
#pragma unroll
        for (int u = 0; u < 8; u++) outZ[f0 + u] = acc[u];
    }
}

// ---------------- gather-mean + combine ------------------------------------
// One warp per node: 32 lanes x float2 = 256B row gather per edge.
// out[i] = mean_{j in in(i)} Y[j] + bias + Z[i]   (+ relu for layer 0)
// LAYER==0 writes g_h (with relu); LAYER==1 writes the Out param (d_out).
template <int LAYER>
__global__ void __launch_bounds__(256) k_agg(
    const float* __restrict__ bias,
    float* __restrict__ OutParam)
{
    int gwarp = (blockIdx.x * blockDim.x + threadIdx.x) >> 5;
    int lane  = threadIdx.x & 31;
    if (gwarp >= N_NODES) return;

    int beg = g_off[gwarp];
    int end = g_off[gwarp + 1];

    const float* Ysrc = (const float*)g_y;

    float acc0 = 0.0f, acc1 = 0.0f;

    for (int j = beg; j < end; j += 32) {
        int idx = 0;
        if (j + lane < end) idx = g_src_sorted[j + lane];
        int m = min(32, end - j);
        int t = 0;
        // unrolled by 4 for memory-level parallelism
        for (; t + 4 <= m; t += 4) {
            int s0 = __shfl_sync(0xffffffffu, idx, t);
            int s1 = __shfl_sync(0xffffffffu, idx, t + 1);
            int s2 = __shfl_sync(0xffffffffu, idx, t + 2);
            int s3 = __shfl_sync(0xffffffffu, idx, t + 3);
            float2 v0 = *(const float2*)(Ysrc + (size_t)s0 * D + 2 * lane);
            float2 v1 = *(const float2*)(Ysrc + (size_t)s1 * D + 2 * lane);
            float2 v2 = *(const float2*)(Ysrc + (size_t)s2 * D + 2 * lane);
            float2 v3 = *(const float2*)(Ysrc + (size_t)s3 * D + 2 * lane);
            acc0 += v0.x + v1.x + v2.x + v3.x;
            acc1 += v0.y + v1.y + v2.y + v3.y;
        }
        for (; t < m; t++) {
            int s = __shfl_sync(0xffffffffu, idx, t);
            float2 v = *(const float2*)(Ysrc + (size_t)s * D + 2 * lane);
            acc0 += v.x;
            acc1 += v.y;
        }
    }

    float inv = (end > beg) ? 1.0f / (float)(end - beg) : 0.0f;
    float2 z = *(const float2*)((const float*)g_z + (size_t)gwarp * D + 2 * lane);
    float o0 = acc0 * inv + bias[2 * lane]     + z.x;
    float o1 = acc1 * inv + bias[2 * lane + 1] + z.y;

    float* Out = (LAYER == 0) ? (float*)g_h : OutParam;
    if (LAYER == 0) { o0 = fmaxf(o0, 0.0f); o1 = fmaxf(o1, 0.0f); }
    *(float2*)(Out + (size_t)gwarp * D + 2 * lane) = make_float2(o0, o1);
}

// ---------------- launch ----------------------------------------------------
extern "C" void kernel_launch(void* const* d_in, const int* in_sizes, int n_in,
                              void* d_out, int out_size)
{
    const float* x   = (const float*)d_in[0];
    const int*   ei  = (const int*)d_in[1];     // edge_index (int32; probe handles int64)
    const float* wl1 = (const float*)d_in[2];
    const float* bl1 = (const float*)d_in[3];
    const float* wr1 = (const float*)d_in[4];
    const float* wl2 = (const float*)d_in[5];
    const float* bl2 = (const float*)d_in[6];
    const float* wr2 = (const float*)d_in[7];
    float* out = (float*)d_out;

    const int TB = 256;
    int nbN = (N_NODES + TB - 1) / TB;        // 391
    int nbE = (E_EDGES + TB - 1) / TB;        // 6250
    int nbAgg = (N_NODES * 32 + TB - 1) / TB; // 12500

    // CSR build (shared by both layers)
    k_detect<<<1, 32>>>(ei);
    k_zero_cnt<<<nbN, TB>>>();
    k_hist<<<nbE, TB>>>(ei);
    k_scan1<<<NB_SCAN, SCAN_T>>>();
    k_scan2<<<1, 32>>>();
    k_scan3<<<NB_SCAN, SCAN_T>>>();
    k_scatter<<<nbE, TB>>>(ei);

    // Layer 1: y = x@wl1^T, z = x@wr1^T ; h = relu(mean_agg(y) + b1 + z)
    k_gemm_dual<0><<<nbN, TB>>>(x, wl1, wr1);
    k_agg<0><<<nbAgg, TB>>>(bl1, nullptr);

    // Layer 2: y = h@wl2^T, z = h@wr2^T ; out = mean_agg(y) + b2 + z
    k_gemm_dual<1><<<nbN, TB>>>(nullptr, wl2, wr2);
    k_agg<1><<<nbAgg, TB>>>(bl2, out);
}

// round 10
// speedup vs baseline: 1.1319x; 1.1319x over previous
#include <cuda_runtime.h>
#include <cuda_bf16.h>
#include <cstdint>

#define N_NODES 100000
#define E_EDGES 1600000
#define D 64

#define SCAN_T 256
#define SCAN_ELEMS 2048                 // 8 per thread
#define NB_SCAN ((N_NODES + SCAN_ELEMS - 1) / SCAN_ELEMS)   // 49

typedef unsigned long long ull;

// ---------------- scratch (device globals; no allocation allowed) ----------
__device__ int   g_cnt[N_NODES];
__device__ int   g_off[N_NODES + 1];
__device__ int   g_cursor[N_NODES];
__device__ int   g_src_sorted[E_EDGES];
__device__ int   g_partial[64];
__device__ int   g_is64;                 // 1 if edge_index is int64, 0 if int32
__device__ float g_y[(size_t)N_NODES * D];
__device__ float g_z[(size_t)N_NODES * D];
__device__ float g_h[(size_t)N_NODES * D];

// ---------------- f32x2 packed helpers (Blackwell FFMA2) --------------------
__device__ __forceinline__ void fma2(ull& d, ull a, ull b) {
    asm("fma.rn.f32x2 %0, %1, %2, %0;" : "+l"(d) : "l"(a), "l"(b));
}
__device__ __forceinline__ float2 u2f2(ull v) {
    float2 r;
    asm("mov.b64 {%0, %1}, %2;" : "=f"(r.x), "=f"(r.y) : "l"(v));
    return r;
}

// ---------------- edge_index layout probe ----------------------------------
// int64 indices < 2^31 -> every high word is 0; int32 -> "high words" are
// random indices, nonzero w.h.p.
__global__ void k_detect(const int* __restrict__ ei32) {
    if (threadIdx.x == 0 && blockIdx.x == 0) {
        int nz_hi = 0;
#pragma unroll 1
        for (int k = 0; k < 64; k++) {
            if (ei32[2 * k + 1] != 0) nz_hi++;
        }
        g_is64 = (nz_hi == 0) ? 1 : 0;
    }
}

__device__ __forceinline__ int edge_val(const int* ei32, long long idx) {
    if (g_is64) return (int)((const long long*)ei32)[idx];
    return ei32[idx];
}

// ---------------- CSR build ------------------------------------------------
__global__ void k_zero_cnt() {
    int i = blockIdx.x * blockDim.x + threadIdx.x;
    if (i < N_NODES) g_cnt[i] = 0;
}

__global__ void k_hist(const int* __restrict__ ei32) {
    int e = blockIdx.x * blockDim.x + threadIdx.x;
    if (e < E_EDGES) {
        int d = edge_val(ei32, (long long)E_EDGES + e);   // dst
        atomicAdd(&g_cnt[d], 1);
    }
}

__global__ void k_scan1() {
    int base = blockIdx.x * SCAN_ELEMS + threadIdx.x * 8;
    int s = 0;
#pragma unroll
    for (int u = 0; u < 8; u++) {
        int i = base + u;
        if (i < N_NODES) s += g_cnt[i];
    }
    __shared__ int sh[SCAN_T];
    sh[threadIdx.x] = s;
    __syncthreads();
    for (int st = SCAN_T / 2; st > 0; st >>= 1) {
        if (threadIdx.x < st) sh[threadIdx.x] += sh[threadIdx.x + st];
        __syncthreads();
    }
    if (threadIdx.x == 0) g_partial[blockIdx.x] = sh[0];
}

__global__ void k_scan2() {
    if (threadIdx.x == 0 && blockIdx.x == 0) {
        int acc = 0;
        for (int b = 0; b < NB_SCAN; b++) {
            int v = g_partial[b];
            g_partial[b] = acc;
            acc += v;
        }
        g_off[N_NODES] = acc;   // == E_EDGES
    }
}

__global__ void k_scan3() {
    __shared__ int sh[SCAN_T];
    int base = blockIdx.x * SCAN_ELEMS + threadIdx.x * 8;
    int loc[8];
    int s = 0;
#pragma unroll
    for (int u = 0; u < 8; u++) {
        int i = base + u;
        loc[u] = (i < N_NODES) ? g_cnt[i] : 0;
        s += loc[u];
    }
    sh[threadIdx.x] = s;
    __syncthreads();
    for (int st = 1; st < SCAN_T; st <<= 1) {
        int v = 0;
        if (threadIdx.x >= st) v = sh[threadIdx.x - st];
        __syncthreads();
        sh[threadIdx.x] += v;
        __syncthreads();
    }
    int pre = g_partial[blockIdx.x] + sh[threadIdx.x] - s;  // exclusive prefix
#pragma unroll
    for (int u = 0; u < 8; u++) {
        int i = base + u;
        if (i < N_NODES) {
            g_off[i] = pre;
            g_cursor[i] = pre;
            pre += loc[u];
        }
    }
}

__global__ void k_scatter(const int* __restrict__ ei32) {
    int e = blockIdx.x * blockDim.x + threadIdx.x;
    if (e < E_EDGES) {
        int d = edge_val(ei32, (long long)E_EDGES + e);
        int s = edge_val(ei32, e);
        int p = atomicAdd(&g_cursor[d], 1);
        g_src_sorted[p] = s;
    }
}

// ---------------- fused dual GEMM with packed f32x2 FMA ---------------------
// Y = X @ Wl^T, Z = X @ Wr^T. One thread per node row.
// Packing is along K: a = {x_k, x_{k+1}} (free: X row reread as u64),
// b = {w[f][k], w[f][k+1]} (free: adjacent in row-major W), so the inner loop
// is pure LDS.128 (broadcast) + FFMA2 — half the FMA-pipe issue slots of the
// scalar version. Horizontal lo+hi add per output at the end.
__device__ __forceinline__ void gemm_row_f32x2(
    const float* __restrict__ Wsh,     // [64,64] row-major in smem
    const ull* __restrict__ xq,        // 32 packed k-pairs of this row
    float* __restrict__ out)
{
#pragma unroll 1
    for (int f0 = 0; f0 < D; f0 += 8) {
        ull acc[8];
#pragma unroll
        for (int u = 0; u < 8; u++) acc[u] = 0ULL;   // {0.f, 0.f}
#pragma unroll
        for (int k4 = 0; k4 < 16; k4++) {
#pragma unroll
            for (int u = 0; u < 8; u++) {
                ulonglong2 w = *(const ulonglong2*)&Wsh[(f0 + u) * D + k4 * 4];
                fma2(acc[u], xq[2 * k4],     w.x);
                fma2(acc[u], xq[2 * k4 + 1], w.y);
            }
        }
        float o[8];
#pragma unroll
        for (int u = 0; u < 8; u++) {
            float2 p = u2f2(acc[u]);
            o[u] = p.x + p.y;
        }
        *(float4*)&out[f0]     = make_float4(o[0], o[1], o[2], o[3]);
        *(float4*)&out[f0 + 4] = make_float4(o[4], o[5], o[6], o[7]);
    }
}

template <int LAYER>
__global__ void __launch_bounds__(128) k_gemm_dual(
    const float* __restrict__ Xin,
    const float* __restrict__ Wl,   // [64,64] row-major [out,in]
    const float* __restrict__ Wr)
{
    __shared__ float swl[D * D];
    __shared__ float swr[D * D];
    for (int i = threadIdx.x; i < D * D; i += 128) {
        swl[i] = Wl[i];
        swr[i] = Wr[i];
    }
    __syncthreads();

    int row = blockIdx.x * 128 + threadIdx.x;
    if (row >= N_NODES) return;

    const float* X = (LAYER == 0) ? Xin : (const float*)g_h;

    ull xq[32];
    const ulonglong2* xp = (const ulonglong2*)(X + (size_t)row * D);
#pragma unroll
    for (int i = 0; i < 16; i++) {
        ulonglong2 t = xp[i];
        xq[2 * i]     = t.x;
        xq[2 * i + 1] = t.y;
    }

    gemm_row_f32x2(swl, xq, g_y + (size_t)row * D);
    gemm_row_f32x2(swr, xq, g_z + (size_t)row * D);
}

// ---------------- gather-mean + combine ------------------------------------
// One warp per node; HALF-warp (16 lanes x float4 = 256B) per gathered row,
// so each warp keeps 2 edges per step and (with the x4 unroll) 8 LDG.128 in
// flight. Cross-half reduction via 4 shfl.xor(16) at the end.
// out[i] = mean_{j in in(i)} Y[j] + bias + Z[i]   (+ relu for layer 0)
template <int LAYER>
__global__ void __launch_bounds__(256) k_agg(
    const float* __restrict__ bias,
    float* __restrict__ OutParam)
{
    int gwarp = (blockIdx.x * blockDim.x + threadIdx.x) >> 5;
    int lane  = threadIdx.x & 31;
    if (gwarp >= N_NODES) return;

    int half = lane >> 4;     // which edge of the pair
    int sub  = lane & 15;     // 16B chunk within the row

    int beg = g_off[gwarp];
    int end = g_off[gwarp + 1];

    const float* Ybase = (const float*)g_y + sub * 4;

    float4 acc = make_float4(0.f, 0.f, 0.f, 0.f);

    for (int j = beg; j < end; j += 32) {
        int idx = (j + lane < end) ? g_src_sorted[j + lane] : 0;
        int m = min(32, end - j);
        int t = 0;
        // 8 edges per iteration: 4 per half-warp, 4 LDG.128 in flight per lane
        for (; t + 8 <= m; t += 8) {
            int s0 = __shfl_sync(0xffffffffu, idx, t     + half);
            int s1 = __shfl_sync(0xffffffffu, idx, t + 2 + half);
            int s2 = __shfl_sync(0xffffffffu, idx, t + 4 + half);
            int s3 = __shfl_sync(0xffffffffu, idx, t + 6 + half);
            float4 v0 = *(const float4*)(Ybase + (size_t)s0 * D);
            float4 v1 = *(const float4*)(Ybase + (size_t)s1 * D);
            float4 v2 = *(const float4*)(Ybase + (size_t)s2 * D);
            float4 v3 = *(const float4*)(Ybase + (size_t)s3 * D);
            float4 s01 = make_float4(v0.x + v1.x, v0.y + v1.y, v0.z + v1.z, v0.w + v1.w);
            float4 s23 = make_float4(v2.x + v3.x, v2.y + v3.y, v2.z + v3.z, v2.w + v3.w);
            acc.x += s01.x + s23.x;
            acc.y += s01.y + s23.y;
            acc.z += s01.z + s23.z;
            acc.w += s01.w + s23.w;
        }
        // tail, 2 edges per step (shfl unconditional: full-warp participation)
        for (; t < m; t += 2) {
            int s = __shfl_sync(0xffffffffu, idx, min(t + half, m - 1));
            if (t + half < m) {
                float4 v = *(const float4*)(Ybase + (size_t)s * D);
                acc.x += v.x; acc.y += v.y; acc.z += v.z; acc.w += v.w;
            }
        }
    }

    // combine the two half-warp partial sums
    acc.x += __shfl_xor_sync(0xffffffffu, acc.x, 16);
    acc.y += __shfl_xor_sync(0xffffffffu, acc.y, 16);
    acc.z += __shfl_xor_sync(0xffffffffu, acc.z, 16);
    acc.w += __shfl_xor_sync(0xffffffffu, acc.w, 16);

    if (half == 0) {
        float inv = (end > beg) ? 1.0f / (float)(end - beg) : 0.0f;
        float4 z = *(const float4*)((const float*)g_z + (size_t)gwarp * D + sub * 4);
        float4 b = *(const float4*)(bias + sub * 4);
        float o0 = acc.x * inv + b.x + z.x;
        float o1 = acc.y * inv + b.y + z.y;
        float o2 = acc.z * inv + b.z + z.z;
        float o3 = acc.w * inv + b.w + z.w;
        float* Out = (LAYER == 0) ? (float*)g_h : OutParam;
        if (LAYER == 0) {
            o0 = fmaxf(o0, 0.0f); o1 = fmaxf(o1, 0.0f);
            o2 = fmaxf(o2, 0.0f); o3 = fmaxf(o3, 0.0f);
        }
        *(float4*)(Out + (size_t)gwarp * D + sub * 4) = make_float4(o0, o1, o2, o3);
    }
}

// ---------------- launch ----------------------------------------------------
extern "C" void kernel_launch(void* const* d_in, const int* in_sizes, int n_in,
                              void* d_out, int out_size)
{
    const float* x   = (const float*)d_in[0];
    const int*   ei  = (const int*)d_in[1];     // edge_index (probe handles int32/int64)
    const float* wl1 = (const float*)d_in[2];
    const float* bl1 = (const float*)d_in[3];
    const float* wr1 = (const float*)d_in[4];
    const float* wl2 = (const float*)d_in[5];
    const float* bl2 = (const float*)d_in[6];
    const float* wr2 = (const float*)d_in[7];
    float* out = (float*)d_out;

    const int TB = 256;
    int nbN   = (N_NODES + TB - 1) / TB;        // 391
    int nbE   = (E_EDGES + TB - 1) / TB;        // 6250
    int nbAgg = (N_NODES * 32 + TB - 1) / TB;   // 12500
    int nbG   = (N_NODES + 127) / 128;          // 782

    // CSR build (shared by both layers)
    k_detect<<<1, 32>>>(ei);
    k_zero_cnt<<<nbN, TB>>>();
    k_hist<<<nbE, TB>>>(ei);
    k_scan1<<<NB_SCAN, SCAN_T>>>();
    k_scan2<<<1, 32>>>();
    k_scan3<<<NB_SCAN, SCAN_T>>>();
    k_scatter<<<nbE, TB>>>(ei);

    // Layer 1: y = x@wl1^T, z = x@wr1^T ; h = relu(mean_agg(y) + b1 + z)
    k_gemm_dual<0><<<nbG, 128>>>(x, wl1, wr1);
    k_agg<0><<<nbAgg, TB>>>(bl1, nullptr);

    // Layer 2: y = h@wl2^T, z = h@wr2^T ; out = mean_agg(y) + b2 + z
    k_gemm_dual<1><<<nbG, 128>>>(nullptr, wl2, wr2);
    k_agg<1><<<nbAgg, TB>>>(bl2, out);
}